// round 6
// baseline (speedup 1.0000x reference)
#include <cuda_runtime.h>
#include <cuda_bf16.h>
#include <math.h>
#include <stdint.h>

// ---------------------------------------------------------------------------
// AttentiveFPConv: out = tanh(x@Wn + bn + aggr@Wg + bg)
//   aggr[u] = sum_{e: row[e]==u} g[col[e]],  g[v] = x[v] * sigmoid((x@Wa+ba)[v])
// N = 40000, E = 640000, D = 128.
// GEMMs: mma.sync m16n8k16 bf16, 2-way hi/lo split (3 terms), fp32 accum.
// Aggregation: CSR build + warp-per-node register gather (no atomics on data).
// ---------------------------------------------------------------------------

#define NODES_MAX 40000
#define EDGES_MAX 640000
#define DIM 128

__device__ float g_yn[NODES_MAX * DIM];
__device__ float g_ga[NODES_MAX * DIM];
__device__ float g_aggr[NODES_MAX * DIM];
__device__ int2  g_eidx[EDGES_MAX];
__device__ int   g_ecol[EDGES_MAX];
__device__ int   g_deg[NODES_MAX + 1];
__device__ int   g_off[NODES_MAX + 1];
__device__ int   g_cursor[NODES_MAX];
__device__ int   g_is64;
// Weights pre-transposed to [n][k], split hi/lo bf16
__device__ __align__(16) __nv_bfloat16 g_wconv[3][2][DIM * DIM];

// ---------------------------------------------------------------------------
__device__ __forceinline__ uint32_t smem_u32(const void* p) {
    uint32_t a;
    asm("{ .reg .u64 t; cvta.to.shared.u64 t, %1; cvt.u32.u64 %0, t; }" : "=r"(a) : "l"(p));
    return a;
}
__device__ __forceinline__ void ldsm4(uint32_t a, uint32_t& r0, uint32_t& r1,
                                      uint32_t& r2, uint32_t& r3) {
    asm volatile("ldmatrix.sync.aligned.m8n8.x4.shared.b16 {%0,%1,%2,%3}, [%4];"
                 : "=r"(r0), "=r"(r1), "=r"(r2), "=r"(r3) : "r"(a));
}
__device__ __forceinline__ void mma16816(float* c, uint32_t a0, uint32_t a1,
                                         uint32_t a2, uint32_t a3,
                                         uint32_t b0, uint32_t b1) {
    asm volatile(
        "mma.sync.aligned.m16n8k16.row.col.f32.bf16.bf16.f32 "
        "{%0,%1,%2,%3}, {%4,%5,%6,%7}, {%8,%9}, {%0,%1,%2,%3};"
        : "+f"(c[0]), "+f"(c[1]), "+f"(c[2]), "+f"(c[3])
        : "r"(a0), "r"(a1), "r"(a2), "r"(a3), "r"(b0), "r"(b1));
}
__device__ __forceinline__ uint32_t pack_bf16x2(float x, float y) {
    __nv_bfloat16 hx = __float2bfloat16(x), hy = __float2bfloat16(y);
    return (uint32_t)*(unsigned short*)&hx | ((uint32_t)*(unsigned short*)&hy << 16);
}

// ---------------------------------------------------------------------------
__global__ void detect_idx_kernel(const int* __restrict__ ei32) {
    if (threadIdx.x == 0 && blockIdx.x == 0) {
        int is64 = 1;
        #pragma unroll
        for (int i = 0; i < 32; i++)
            if (ei32[2 * i + 1] != 0) { is64 = 0; break; }
        g_is64 = is64;
    }
}

__global__ void zero_deg_kernel(int N) {
    int i = blockIdx.x * blockDim.x + threadIdx.x;
    if (i <= N) g_deg[i] = 0;
}

// Pack (row,col) AND histogram rows in one pass.
__global__ __launch_bounds__(256) void pack_hist_kernel(const void* __restrict__ ei, int E) {
    int e = blockIdx.x * blockDim.x + threadIdx.x;
    if (e >= E) return;
    int row, col;
    if (g_is64) {
        const long long* p = (const long long*)ei;
        row = (int)p[e]; col = (int)p[E + e];
    } else {
        const int* p = (const int*)ei;
        row = p[e]; col = p[E + e];
    }
    g_eidx[e] = make_int2(row, col);
    atomicAdd(&g_deg[row], 1);
}

// Single-block exclusive scan of g_deg -> g_off (+ cursor copy).
__global__ __launch_bounds__(1024) void scan_kernel(int N) {
    __shared__ int part[1024];
    int t = threadIdx.x;
    int chunk = (N + 1023) / 1024;
    int start = t * chunk;
    int end = min(start + chunk, N);
    int s = 0;
    for (int i = start; i < end; i++) s += g_deg[i];
    part[t] = s;
    __syncthreads();
    #pragma unroll
    for (int d = 1; d < 1024; d <<= 1) {
        int v = (t >= d) ? part[t - d] : 0;
        __syncthreads();
        part[t] += v;
        __syncthreads();
    }
    int excl = (t == 0) ? 0 : part[t - 1];
    for (int i = start; i < end; i++) {
        int dg = g_deg[i];
        g_off[i] = excl;
        g_cursor[i] = excl;
        excl += dg;
    }
    if (t == 1023) g_off[N] = excl;
}

__global__ __launch_bounds__(256) void fill_csr_kernel(int E) {
    int e = blockIdx.x * blockDim.x + threadIdx.x;
    if (e >= E) return;
    int2 rc = g_eidx[e];
    int pos = atomicAdd(&g_cursor[rc.x], 1);
    g_ecol[pos] = rc.y;
}

// Warp-per-node gather: aggr[u] = sum_{i in [off[u],off[u+1])} g[ecol[i]]
__global__ __launch_bounds__(256) void spmm_kernel(int N) {
    int warp = (int)((blockIdx.x * 256 + threadIdx.x) >> 5);
    if (warp >= N) return;
    int lane = threadIdx.x & 31;
    int beg = g_off[warp], end = g_off[warp + 1];

    float4 acc = make_float4(0.f, 0.f, 0.f, 0.f);
    for (int base = beg; base < end; base += 32) {
        int n = min(32, end - base);
        int c = (base + lane < end) ? g_ecol[base + lane] : 0;
        for (int j = 0; j < n; j++) {
            int col = __shfl_sync(0xffffffffu, c, j);
            float4 v = *(const float4*)(g_ga + (size_t)col * DIM + lane * 4);
            acc.x += v.x; acc.y += v.y; acc.z += v.z; acc.w += v.w;
        }
    }
    *(float4*)(g_aggr + (size_t)warp * DIM + lane * 4) = acc;
}

// ---------------------------------------------------------------------------
// prep weights: W[k][n] -> Bt[n][k] hi/lo bf16 via smem-tile transpose.
// grid = 3 matrices * 8 k-chunks, coalesced loads.
// ---------------------------------------------------------------------------
__global__ __launch_bounds__(256) void prep_weights_kernel(
    const float* __restrict__ Wn, const float* __restrict__ Wg,
    const float* __restrict__ Wa)
{
    int mat = blockIdx.x >> 3;
    int kc  = (blockIdx.x & 7) * 16;
    const float* W = mat == 0 ? Wn : (mat == 1 ? Wg : Wa);
    __shared__ float tile[16][DIM];
    for (int i = threadIdx.x; i < 16 * DIM; i += 256) {
        int kk = i >> 7, n = i & 127;
        tile[kk][n] = W[(size_t)(kc + kk) * DIM + n];
    }
    __syncthreads();
    uint32_t* hi = (uint32_t*)g_wconv[mat][0];
    uint32_t* lo = (uint32_t*)g_wconv[mat][1];
    for (int i = threadIdx.x; i < DIM * 8; i += 256) {
        int n = i >> 3, kp = (i & 7) * 2;
        float v0 = tile[kp][n], v1 = tile[kp + 1][n];
        float h0 = __bfloat162float(__float2bfloat16(v0));
        float h1 = __bfloat162float(__float2bfloat16(v1));
        int idx = (n * DIM + kc + kp) >> 1;
        hi[idx] = pack_bf16x2(h0, h1);
        lo[idx] = pack_bf16x2(v0 - h0, v1 - h1);
    }
}

// ---------------------------------------------------------------------------
// mma.sync GEMM (validated round 4): 128x128 CTA tile, 8 warps 4x2, K resident.
// ---------------------------------------------------------------------------
#define ASTRIDE 272
#define BUF_SZ  (DIM * ASTRIDE)
#define SM_TOTAL (4 * BUF_SZ)

__global__ __launch_bounds__(256) void gemm_mma_fused(
    const float* __restrict__ A, int widx,
    const float* __restrict__ bias, const float* __restrict__ extra,
    float* __restrict__ out, int N, int mode)
{
    extern __shared__ __align__(16) char smem[];
    const uint32_t sb  = smem_u32(smem);
    const uint32_t sAH = sb, sAL = sb + BUF_SZ, sBH = sb + 2 * BUF_SZ, sBL = sb + 3 * BUF_SZ;
    const int tid = threadIdx.x, lane = tid & 31, wid = tid >> 5;
    const int m0 = blockIdx.x * 128;

    for (int i = tid; i < 128 * 32; i += 256) {
        int rl = i >> 5;
        int c4 = (i & 31) * 4;
        int r = m0 + rl; if (r >= N) r = N - 1;
        float4 v = *(const float4*)(A + (size_t)r * DIM + c4);
        float h0 = __bfloat162float(__float2bfloat16(v.x));
        float h1 = __bfloat162float(__float2bfloat16(v.y));
        float h2 = __bfloat162float(__float2bfloat16(v.z));
        float h3 = __bfloat162float(__float2bfloat16(v.w));
        uint2 hv = make_uint2(pack_bf16x2(h0, h1), pack_bf16x2(h2, h3));
        uint2 lv = make_uint2(pack_bf16x2(v.x - h0, v.y - h1),
                              pack_bf16x2(v.z - h2, v.w - h3));
        int off = rl * ASTRIDE + c4 * 2;
        *(uint2*)(smem + off)          = hv;
        *(uint2*)(smem + BUF_SZ + off) = lv;
    }
    {
        const uint4* wh = (const uint4*)g_wconv[widx][0];
        const uint4* wl = (const uint4*)g_wconv[widx][1];
        for (int i = tid; i < 2048; i += 256) {
            int r = i >> 4, c = (i & 15) * 16;
            int off = r * ASTRIDE + c;
            *(uint4*)(smem + 2 * BUF_SZ + off) = wh[i];
            *(uint4*)(smem + 3 * BUF_SZ + off) = wl[i];
        }
    }
    __syncthreads();

    const int wm = wid & 3;
    const int wn = wid >> 2;

    float acc[2][8][4];
    #pragma unroll
    for (int mt = 0; mt < 2; mt++)
        #pragma unroll
        for (int nt = 0; nt < 8; nt++)
            #pragma unroll
            for (int q = 0; q < 4; q++) acc[mt][nt][q] = 0.f;

    for (int s = 0; s < 8; s++) {
        const int k0 = s * 16;
        uint32_t ah[2][4], al[2][4];
        #pragma unroll
        for (int mt = 0; mt < 2; mt++) {
            int row = wm * 32 + mt * 16 + (lane & 15);
            int col = k0 + (lane >> 4) * 8;
            uint32_t off = row * ASTRIDE + col * 2;
            ldsm4(sAH + off, ah[mt][0], ah[mt][1], ah[mt][2], ah[mt][3]);
            ldsm4(sAL + off, al[mt][0], al[mt][1], al[mt][2], al[mt][3]);
        }
        uint32_t bh[8][2], bl[8][2];
        #pragma unroll
        for (int np = 0; np < 4; np++) {
            int g = lane >> 3;
            int row = wn * 64 + np * 16 + (g >> 1) * 8 + (lane & 7);
            int col = k0 + (g & 1) * 8;
            uint32_t off = row * ASTRIDE + col * 2;
            ldsm4(sBH + off, bh[2*np][0], bh[2*np][1], bh[2*np+1][0], bh[2*np+1][1]);
            ldsm4(sBL + off, bl[2*np][0], bl[2*np][1], bl[2*np+1][0], bl[2*np+1][1]);
        }
        #pragma unroll
        for (int mt = 0; mt < 2; mt++)
            #pragma unroll
            for (int nt = 0; nt < 8; nt++) {
                mma16816(acc[mt][nt], ah[mt][0], ah[mt][1], ah[mt][2], ah[mt][3],
                         bh[nt][0], bh[nt][1]);
                mma16816(acc[mt][nt], ah[mt][0], ah[mt][1], ah[mt][2], ah[mt][3],
                         bl[nt][0], bl[nt][1]);
                mma16816(acc[mt][nt], al[mt][0], al[mt][1], al[mt][2], al[mt][3],
                         bh[nt][0], bh[nt][1]);
            }
    }

    float2 bb[8];
    #pragma unroll
    for (int nt = 0; nt < 8; nt++) {
        int n = wn * 64 + nt * 8 + 2 * (lane & 3);
        bb[nt] = *(const float2*)(bias + n);
    }
    #pragma unroll
    for (int mt = 0; mt < 2; mt++) {
        #pragma unroll
        for (int half = 0; half < 2; half++) {
            int m = m0 + wm * 32 + mt * 16 + (lane >> 2) + half * 8;
            if (m >= N) continue;
            #pragma unroll
            for (int nt = 0; nt < 8; nt++) {
                int n = wn * 64 + nt * 8 + 2 * (lane & 3);
                float rx = acc[mt][nt][half * 2 + 0] + bb[nt].x;
                float ry = acc[mt][nt][half * 2 + 1] + bb[nt].y;
                if (mode == 1) {
                    float2 xv = *(const float2*)(extra + (size_t)m * DIM + n);
                    rx = xv.x * (1.f / (1.f + expf(-rx)));
                    ry = xv.y * (1.f / (1.f + expf(-ry)));
                } else if (mode == 2) {
                    float2 yv = *(const float2*)(extra + (size_t)m * DIM + n);
                    rx = tanhf(rx + yv.x);
                    ry = tanhf(ry + yv.y);
                }
                *(float2*)(out + (size_t)m * DIM + n) = make_float2(rx, ry);
            }
        }
    }
}

// ---------------------------------------------------------------------------
extern "C" void kernel_launch(void* const* d_in, const int* in_sizes, int n_in,
                              void* d_out, int out_size)
{
    const float* x    = (const float*)d_in[0];
    const void*  ei   = d_in[1];
    const float* Wn_w = (const float*)d_in[2];
    const float* Wn_b = (const float*)d_in[3];
    const float* Wg_w = (const float*)d_in[4];
    const float* Wg_b = (const float*)d_in[5];
    const float* Wa_w = (const float*)d_in[6];
    const float* Wa_b = (const float*)d_in[7];
    float* out = (float*)d_out;

    const int N = in_sizes[0] / DIM;
    const int E = in_sizes[1] / 2;

    float *p_yn, *p_ga, *p_aggr;
    cudaGetSymbolAddress((void**)&p_yn,   g_yn);
    cudaGetSymbolAddress((void**)&p_ga,   g_ga);
    cudaGetSymbolAddress((void**)&p_aggr, g_aggr);

    cudaFuncSetAttribute(gemm_mma_fused,
                         cudaFuncAttributeMaxDynamicSharedMemorySize, SM_TOTAL);

    // weight prep (coalesced, 24 blocks)
    prep_weights_kernel<<<24, 256>>>(Wn_w, Wg_w, Wa_w);

    // CSR build
    detect_idx_kernel<<<1, 32>>>((const int*)ei);
    zero_deg_kernel<<<(N + 256) / 256, 256>>>(N);
    pack_hist_kernel<<<(E + 255) / 256, 256>>>(ei, E);
    scan_kernel<<<1, 1024>>>(N);
    fill_csr_kernel<<<(E + 255) / 256, 256>>>(E);

    int gblocks = (N + 127) / 128;
    // y_n = x@Wn + bn
    gemm_mma_fused<<<gblocks, 256, SM_TOTAL>>>(x, 0, Wn_b, nullptr, p_yn, N, 0);
    // g = x * sigmoid(x@Wa + ba)
    gemm_mma_fused<<<gblocks, 256, SM_TOTAL>>>(x, 2, Wa_b, x, p_ga, N, 1);

    // aggr = CSR-gather(g)
    {
        long long threads = (long long)N * 32;
        int blocks = (int)((threads + 255) / 256);
        spmm_kernel<<<blocks, 256>>>(N);
    }

    // out = tanh(aggr@Wg + bg + y_n)
    gemm_mma_fused<<<gblocks, 256, SM_TOTAL>>>(p_aggr, 1, Wg_b, p_yn, out, N, 2);
}

// round 8
// speedup vs baseline: 1.1964x; 1.1964x over previous
#include <cuda_runtime.h>
#include <cuda_bf16.h>
#include <math.h>
#include <stdint.h>

// ---------------------------------------------------------------------------
// AttentiveFPConv: out = tanh(x@Wn + bn + aggr@Wg + bg)
//   aggr[u] = sum_{e: row[e]==u} g[col[e]],  g[v] = x[v] * sigmoid((x@Wa+ba)[v])
// N = 40000, E = 640000, D = 128.
// GEMMs: mma.sync m16n8k16 bf16, hi/lo split (3 terms), fp32 accum,
//        fast-math epilogue (EX2/RCP MUFU only).
// Aggregation: warp-per-edge red.global.add.v4.f32 (round-2 proven path).
// ---------------------------------------------------------------------------

#define NODES_MAX 40000
#define EDGES_MAX 640000
#define DIM 128

__device__ float g_yn[NODES_MAX * DIM];
__device__ float g_ga[NODES_MAX * DIM];
__device__ float g_aggr[NODES_MAX * DIM];
__device__ int2  g_eidx[EDGES_MAX];
__device__ int   g_is64;
__device__ __align__(16) __nv_bfloat16 g_wconv[3][2][DIM * DIM];

// ---------------------------------------------------------------------------
__device__ __forceinline__ uint32_t smem_u32(const void* p) {
    uint32_t a;
    asm("{ .reg .u64 t; cvta.to.shared.u64 t, %1; cvt.u32.u64 %0, t; }" : "=r"(a) : "l"(p));
    return a;
}
__device__ __forceinline__ void ldsm4(uint32_t a, uint32_t& r0, uint32_t& r1,
                                      uint32_t& r2, uint32_t& r3) {
    asm volatile("ldmatrix.sync.aligned.m8n8.x4.shared.b16 {%0,%1,%2,%3}, [%4];"
                 : "=r"(r0), "=r"(r1), "=r"(r2), "=r"(r3) : "r"(a));
}
__device__ __forceinline__ void mma16816(float* c, uint32_t a0, uint32_t a1,
                                         uint32_t a2, uint32_t a3,
                                         uint32_t b0, uint32_t b1) {
    asm volatile(
        "mma.sync.aligned.m16n8k16.row.col.f32.bf16.bf16.f32 "
        "{%0,%1,%2,%3}, {%4,%5,%6,%7}, {%8,%9}, {%0,%1,%2,%3};"
        : "+f"(c[0]), "+f"(c[1]), "+f"(c[2]), "+f"(c[3])
        : "r"(a0), "r"(a1), "r"(a2), "r"(a3), "r"(b0), "r"(b1));
}
__device__ __forceinline__ uint32_t pack_bf16x2(float x, float y) {
    __nv_bfloat16 hx = __float2bfloat16(x), hy = __float2bfloat16(y);
    return (uint32_t)*(unsigned short*)&hx | ((uint32_t)*(unsigned short*)&hy << 16);
}
// Fast sigmoid: 1 EX2 + 1 RCP, rel err ~2^-21.
__device__ __forceinline__ float sigmoid_fast(float x) {
    float e = __expf(-x);
    return __fdividef(1.f, 1.f + e);
}
// Fast tanh: tanh(x) = (1-e)/(1+e), e = exp(-2x). 1 EX2 + 1 RCP.
__device__ __forceinline__ float tanh_fast(float x) {
    float e = __expf(-2.f * x);
    return (1.f - e) * __fdividef(1.f, 1.f + e);
}

// ---------------------------------------------------------------------------
__global__ void zero_aggr_kernel(int total_f4) {
    int i = blockIdx.x * blockDim.x + threadIdx.x;
    if (i < total_f4)
        ((float4*)g_aggr)[i] = make_float4(0.f, 0.f, 0.f, 0.f);
}

__global__ void detect_idx_kernel(const int* __restrict__ ei32) {
    if (threadIdx.x == 0 && blockIdx.x == 0) {
        int is64 = 1;
        #pragma unroll
        for (int i = 0; i < 32; i++)
            if (ei32[2 * i + 1] != 0) { is64 = 0; break; }
        g_is64 = is64;
    }
}

__global__ __launch_bounds__(256) void pack_idx_kernel(const void* __restrict__ ei, int E) {
    int e = blockIdx.x * blockDim.x + threadIdx.x;
    if (e >= E) return;
    int row, col;
    if (g_is64) {
        const long long* p = (const long long*)ei;
        row = (int)p[e]; col = (int)p[E + e];
    } else {
        const int* p = (const int*)ei;
        row = p[e]; col = p[E + e];
    }
    g_eidx[e] = make_int2(row, col);
}

// prep weights: W[k][n] -> Bt[n][k] hi/lo bf16, coalesced via smem transpose.
__global__ __launch_bounds__(256) void prep_weights_kernel(
    const float* __restrict__ Wn, const float* __restrict__ Wg,
    const float* __restrict__ Wa)
{
    int mat = blockIdx.x >> 3;
    int kc  = (blockIdx.x & 7) * 16;
    const float* W = mat == 0 ? Wn : (mat == 1 ? Wg : Wa);
    __shared__ float tile[16][DIM];
    for (int i = threadIdx.x; i < 16 * DIM; i += 256) {
        int kk = i >> 7, n = i & 127;
        tile[kk][n] = W[(size_t)(kc + kk) * DIM + n];
    }
    __syncthreads();
    uint32_t* hi = (uint32_t*)g_wconv[mat][0];
    uint32_t* lo = (uint32_t*)g_wconv[mat][1];
    for (int i = threadIdx.x; i < DIM * 8; i += 256) {
        int n = i >> 3, kp = (i & 7) * 2;
        float v0 = tile[kp][n], v1 = tile[kp + 1][n];
        float h0 = __bfloat162float(__float2bfloat16(v0));
        float h1 = __bfloat162float(__float2bfloat16(v1));
        int idx = (n * DIM + kc + kp) >> 1;
        hi[idx] = pack_bf16x2(h0, h1);
        lo[idx] = pack_bf16x2(v0 - h0, v1 - h1);
    }
}

// ---------------------------------------------------------------------------
// mma.sync GEMM: 128x128 CTA tile, 8 warps 4(M)x2(N), K=128 resident.
//   mode 0: +bias; mode 1: extra*sigmoid(acc+bias); mode 2: tanh(acc+bias+extra)
// ---------------------------------------------------------------------------
#define ASTRIDE 272
#define BUF_SZ  (DIM * ASTRIDE)
#define SM_TOTAL (4 * BUF_SZ)

__global__ __launch_bounds__(256) void gemm_mma_fused(
    const float* __restrict__ A, int widx,
    const float* __restrict__ bias, const float* __restrict__ extra,
    float* __restrict__ out, int N, int mode)
{
    extern __shared__ __align__(16) char smem[];
    const uint32_t sb  = smem_u32(smem);
    const uint32_t sAH = sb, sAL = sb + BUF_SZ, sBH = sb + 2 * BUF_SZ, sBL = sb + 3 * BUF_SZ;
    const int tid = threadIdx.x, lane = tid & 31, wid = tid >> 5;
    const int m0 = blockIdx.x * 128;

    for (int i = tid; i < 128 * 32; i += 256) {
        int rl = i >> 5;
        int c4 = (i & 31) * 4;
        int r = m0 + rl; if (r >= N) r = N - 1;
        float4 v = *(const float4*)(A + (size_t)r * DIM + c4);
        float h0 = __bfloat162float(__float2bfloat16(v.x));
        float h1 = __bfloat162float(__float2bfloat16(v.y));
        float h2 = __bfloat162float(__float2bfloat16(v.z));
        float h3 = __bfloat162float(__float2bfloat16(v.w));
        uint2 hv = make_uint2(pack_bf16x2(h0, h1), pack_bf16x2(h2, h3));
        uint2 lv = make_uint2(pack_bf16x2(v.x - h0, v.y - h1),
                              pack_bf16x2(v.z - h2, v.w - h3));
        int off = rl * ASTRIDE + c4 * 2;
        *(uint2*)(smem + off)          = hv;
        *(uint2*)(smem + BUF_SZ + off) = lv;
    }
    {
        const uint4* wh = (const uint4*)g_wconv[widx][0];
        const uint4* wl = (const uint4*)g_wconv[widx][1];
        for (int i = tid; i < 2048; i += 256) {
            int r = i >> 4, c = (i & 15) * 16;
            int off = r * ASTRIDE + c;
            *(uint4*)(smem + 2 * BUF_SZ + off) = wh[i];
            *(uint4*)(smem + 3 * BUF_SZ + off) = wl[i];
        }
    }
    __syncthreads();

    const int wm = wid & 3;
    const int wn = wid >> 2;

    float acc[2][8][4];
    #pragma unroll
    for (int mt = 0; mt < 2; mt++)
        #pragma unroll
        for (int nt = 0; nt < 8; nt++)
            #pragma unroll
            for (int q = 0; q < 4; q++) acc[mt][nt][q] = 0.f;

    for (int s = 0; s < 8; s++) {
        const int k0 = s * 16;
        uint32_t ah[2][4], al[2][4];
        #pragma unroll
        for (int mt = 0; mt < 2; mt++) {
            int row = wm * 32 + mt * 16 + (lane & 15);
            int col = k0 + (lane >> 4) * 8;
            uint32_t off = row * ASTRIDE + col * 2;
            ldsm4(sAH + off, ah[mt][0], ah[mt][1], ah[mt][2], ah[mt][3]);
            ldsm4(sAL + off, al[mt][0], al[mt][1], al[mt][2], al[mt][3]);
        }
        uint32_t bh[8][2], bl[8][2];
        #pragma unroll
        for (int np = 0; np < 4; np++) {
            int g = lane >> 3;
            int row = wn * 64 + np * 16 + (g >> 1) * 8 + (lane & 7);
            int col = k0 + (g & 1) * 8;
            uint32_t off = row * ASTRIDE + col * 2;
            ldsm4(sBH + off, bh[2*np][0], bh[2*np][1], bh[2*np+1][0], bh[2*np+1][1]);
            ldsm4(sBL + off, bl[2*np][0], bl[2*np][1], bl[2*np+1][0], bl[2*np+1][1]);
        }
        #pragma unroll
        for (int mt = 0; mt < 2; mt++)
            #pragma unroll
            for (int nt = 0; nt < 8; nt++) {
                mma16816(acc[mt][nt], ah[mt][0], ah[mt][1], ah[mt][2], ah[mt][3],
                         bh[nt][0], bh[nt][1]);
                mma16816(acc[mt][nt], ah[mt][0], ah[mt][1], ah[mt][2], ah[mt][3],
                         bl[nt][0], bl[nt][1]);
                mma16816(acc[mt][nt], al[mt][0], al[mt][1], al[mt][2], al[mt][3],
                         bh[nt][0], bh[nt][1]);
            }
    }

    float2 bb[8];
    #pragma unroll
    for (int nt = 0; nt < 8; nt++) {
        int n = wn * 64 + nt * 8 + 2 * (lane & 3);
        bb[nt] = *(const float2*)(bias + n);
    }
    #pragma unroll
    for (int mt = 0; mt < 2; mt++) {
        #pragma unroll
        for (int half = 0; half < 2; half++) {
            int m = m0 + wm * 32 + mt * 16 + (lane >> 2) + half * 8;
            if (m >= N) continue;
            #pragma unroll
            for (int nt = 0; nt < 8; nt++) {
                int n = wn * 64 + nt * 8 + 2 * (lane & 3);
                float rx = acc[mt][nt][half * 2 + 0] + bb[nt].x;
                float ry = acc[mt][nt][half * 2 + 1] + bb[nt].y;
                if (mode == 1) {
                    float2 xv = *(const float2*)(extra + (size_t)m * DIM + n);
                    rx = xv.x * sigmoid_fast(rx);
                    ry = xv.y * sigmoid_fast(ry);
                } else if (mode == 2) {
                    float2 yv = *(const float2*)(extra + (size_t)m * DIM + n);
                    rx = tanh_fast(rx + yv.x);
                    ry = tanh_fast(ry + yv.y);
                }
                *(float2*)(out + (size_t)m * DIM + n) = make_float2(rx, ry);
            }
        }
    }
}

// ---------------------------------------------------------------------------
// Edge scatter: one warp per edge, red.global.add.v4.f32 per lane.
// ---------------------------------------------------------------------------
__global__ __launch_bounds__(256) void edge_scatter_kernel(int E)
{
    int warp = (int)((blockIdx.x * 256 + threadIdx.x) >> 5);
    if (warp >= E) return;
    int lane = threadIdx.x & 31;

    int2 rc = g_eidx[warp];
    const float* src = g_ga + (size_t)rc.y * DIM + lane * 4;
    float* dst       = g_aggr + (size_t)rc.x * DIM + lane * 4;

    float4 v = *(const float4*)src;
    asm volatile("red.global.add.v4.f32 [%0], {%1, %2, %3, %4};"
                 :: "l"(dst), "f"(v.x), "f"(v.y), "f"(v.z), "f"(v.w)
                 : "memory");
}

// ---------------------------------------------------------------------------
extern "C" void kernel_launch(void* const* d_in, const int* in_sizes, int n_in,
                              void* d_out, int out_size)
{
    const float* x    = (const float*)d_in[0];
    const void*  ei   = d_in[1];
    const float* Wn_w = (const float*)d_in[2];
    const float* Wn_b = (const float*)d_in[3];
    const float* Wg_w = (const float*)d_in[4];
    const float* Wg_b = (const float*)d_in[5];
    const float* Wa_w = (const float*)d_in[6];
    const float* Wa_b = (const float*)d_in[7];
    float* out = (float*)d_out;

    const int N = in_sizes[0] / DIM;
    const int E = in_sizes[1] / 2;

    float *p_yn, *p_ga, *p_aggr;
    cudaGetSymbolAddress((void**)&p_yn,   g_yn);
    cudaGetSymbolAddress((void**)&p_ga,   g_ga);
    cudaGetSymbolAddress((void**)&p_aggr, g_aggr);

    cudaFuncSetAttribute(gemm_mma_fused,
                         cudaFuncAttributeMaxDynamicSharedMemorySize, SM_TOTAL);

    prep_weights_kernel<<<24, 256>>>(Wn_w, Wg_w, Wa_w);
    {
        int total_f4 = N * DIM / 4;
        zero_aggr_kernel<<<(total_f4 + 255) / 256, 256>>>(total_f4);
    }
    detect_idx_kernel<<<1, 32>>>((const int*)ei);
    pack_idx_kernel<<<(E + 255) / 256, 256>>>(ei, E);

    int gblocks = (N + 127) / 128;
    // y_n = x@Wn + bn
    gemm_mma_fused<<<gblocks, 256, SM_TOTAL>>>(x, 0, Wn_b, nullptr, p_yn, N, 0);
    // g = x * sigmoid(x@Wa + ba)
    gemm_mma_fused<<<gblocks, 256, SM_TOTAL>>>(x, 2, Wa_b, x, p_ga, N, 1);

    // aggr[row] += g[col]
    {
        long long threads = (long long)E * 32;
        int blocks = (int)((threads + 255) / 256);
        edge_scatter_kernel<<<blocks, 256>>>(E);
    }

    // out = tanh(aggr@Wg + bg + y_n)
    gemm_mma_fused<<<gblocks, 256, SM_TOTAL>>>(p_aggr, 1, Wg_b, p_yn, out, N, 2);
}

// round 9
// speedup vs baseline: 1.6145x; 1.3494x over previous
#include <cuda_runtime.h>
#include <cuda_bf16.h>
#include <math.h>
#include <stdint.h>

// ---------------------------------------------------------------------------
// AttentiveFPConv: out = tanh(x@Wn + bn + aggr@Wg + bg)
//   aggr[u] = sum_{e: row[e]==u} g[col[e]],  g[v] = x[v] * sigmoid((x@Wa+ba)[v])
// N = 40000, E = 640000, D = 128.
// GEMMs: mma.sync m16n8k16 bf16, hi/lo split (3 terms), fp32 accum,
//        K-split SMEM (72KB) for 2 CTAs/SM, fast-math epilogue.
// Aggregation: warp-per-edge red.global.add.v4.f32.
// ---------------------------------------------------------------------------

#define NODES_MAX 40000
#define EDGES_MAX 640000
#define DIM 128

__device__ float g_yn[NODES_MAX * DIM];
__device__ float g_ga[NODES_MAX * DIM];
__device__ float g_aggr[NODES_MAX * DIM];
__device__ int2  g_eidx[EDGES_MAX];
__device__ int   g_is64;
__device__ __align__(16) __nv_bfloat16 g_wconv[3][2][DIM * DIM];

// ---------------------------------------------------------------------------
__device__ __forceinline__ uint32_t smem_u32(const void* p) {
    uint32_t a;
    asm("{ .reg .u64 t; cvta.to.shared.u64 t, %1; cvt.u32.u64 %0, t; }" : "=r"(a) : "l"(p));
    return a;
}
__device__ __forceinline__ void ldsm4(uint32_t a, uint32_t& r0, uint32_t& r1,
                                      uint32_t& r2, uint32_t& r3) {
    asm volatile("ldmatrix.sync.aligned.m8n8.x4.shared.b16 {%0,%1,%2,%3}, [%4];"
                 : "=r"(r0), "=r"(r1), "=r"(r2), "=r"(r3) : "r"(a));
}
__device__ __forceinline__ void mma16816(float* c, uint32_t a0, uint32_t a1,
                                         uint32_t a2, uint32_t a3,
                                         uint32_t b0, uint32_t b1) {
    asm volatile(
        "mma.sync.aligned.m16n8k16.row.col.f32.bf16.bf16.f32 "
        "{%0,%1,%2,%3}, {%4,%5,%6,%7}, {%8,%9}, {%0,%1,%2,%3};"
        : "+f"(c[0]), "+f"(c[1]), "+f"(c[2]), "+f"(c[3])
        : "r"(a0), "r"(a1), "r"(a2), "r"(a3), "r"(b0), "r"(b1));
}
__device__ __forceinline__ uint32_t pack_bf16x2(float x, float y) {
    __nv_bfloat16 hx = __float2bfloat16(x), hy = __float2bfloat16(y);
    return (uint32_t)*(unsigned short*)&hx | ((uint32_t)*(unsigned short*)&hy << 16);
}
__device__ __forceinline__ float sigmoid_fast(float x) {
    float e = __expf(-x);
    return __fdividef(1.f, 1.f + e);
}
__device__ __forceinline__ float tanh_fast(float x) {
    float e = __expf(-2.f * x);
    return (1.f - e) * __fdividef(1.f, 1.f + e);
}

// ---------------------------------------------------------------------------
__global__ void detect_idx_kernel(const int* __restrict__ ei32) {
    if (threadIdx.x == 0 && blockIdx.x == 0) {
        int is64 = 1;
        #pragma unroll
        for (int i = 0; i < 32; i++)
            if (ei32[2 * i + 1] != 0) { is64 = 0; break; }
        g_is64 = is64;
    }
}

// Fused: zero aggr (NF4 float4s) + pack edge indices (E int2s).
__global__ __launch_bounds__(256) void zero_pack_kernel(const void* __restrict__ ei,
                                                        int E, int NF4) {
    int i = blockIdx.x * blockDim.x + threadIdx.x;
    if (i < NF4)
        ((float4*)g_aggr)[i] = make_float4(0.f, 0.f, 0.f, 0.f);
    if (i < E) {
        int row, col;
        if (g_is64) {
            const long long* p = (const long long*)ei;
            row = (int)p[i]; col = (int)p[E + i];
        } else {
            const int* p = (const int*)ei;
            row = p[i]; col = p[E + i];
        }
        g_eidx[i] = make_int2(row, col);
    }
}

// prep weights: W[k][n] -> Bt[n][k] hi/lo bf16, coalesced via smem transpose.
__global__ __launch_bounds__(256) void prep_weights_kernel(
    const float* __restrict__ Wn, const float* __restrict__ Wg,
    const float* __restrict__ Wa)
{
    int mat = blockIdx.x >> 3;
    int kc  = (blockIdx.x & 7) * 16;
    const float* W = mat == 0 ? Wn : (mat == 1 ? Wg : Wa);
    __shared__ float tile[16][DIM];
    for (int i = threadIdx.x; i < 16 * DIM; i += 256) {
        int kk = i >> 7, n = i & 127;
        tile[kk][n] = W[(size_t)(kc + kk) * DIM + n];
    }
    __syncthreads();
    uint32_t* hi = (uint32_t*)g_wconv[mat][0];
    uint32_t* lo = (uint32_t*)g_wconv[mat][1];
    for (int i = threadIdx.x; i < DIM * 8; i += 256) {
        int n = i >> 3, kp = (i & 7) * 2;
        float v0 = tile[kp][n], v1 = tile[kp + 1][n];
        float h0 = __bfloat162float(__float2bfloat16(v0));
        float h1 = __bfloat162float(__float2bfloat16(v1));
        int idx = (n * DIM + kc + kp) >> 1;
        hi[idx] = pack_bf16x2(h0, h1);
        lo[idx] = pack_bf16x2(v0 - h0, v1 - h1);
    }
}

// ---------------------------------------------------------------------------
// mma.sync GEMM: 128x128 CTA tile, 8 warps 4(M)x2(N), K split in two halves
// of 64 so SMEM = 72KB -> 2 CTAs/SM.
//   mode 0: +bias; mode 1: extra*sigmoid(acc+bias); mode 2: tanh(acc+bias+extra)
// ---------------------------------------------------------------------------
#define KH 64
#define BSTRIDE 144                    // bytes/row: 64 bf16 + 8 pad (bank+4/row)
#define HBUF (DIM * BSTRIDE)           // 18432
#define SM_TOTAL (4 * HBUF)            // 73728

__global__ __launch_bounds__(256, 2) void gemm_mma_fused(
    const float* __restrict__ A, int widx,
    const float* __restrict__ bias, const float* __restrict__ extra,
    float* __restrict__ out, int N, int mode)
{
    extern __shared__ __align__(16) char smem[];
    const uint32_t sb  = smem_u32(smem);
    const uint32_t sAH = sb, sAL = sb + HBUF, sBH = sb + 2 * HBUF, sBL = sb + 3 * HBUF;
    const int tid = threadIdx.x, lane = tid & 31, wid = tid >> 5;
    const int m0 = blockIdx.x * 128;
    const int wm = wid & 3;
    const int wn = wid >> 2;

    float acc[2][8][4];
    #pragma unroll
    for (int mt = 0; mt < 2; mt++)
        #pragma unroll
        for (int nt = 0; nt < 8; nt++)
            #pragma unroll
            for (int q = 0; q < 4; q++) acc[mt][nt][q] = 0.f;

    #pragma unroll 1
    for (int h = 0; h < 2; h++) {
        if (h) __syncthreads();   // prior half's ldsm reads complete

        // A half: 128 rows x 16 float (64 cols), split hi/lo
        for (int i = tid; i < 128 * 16; i += 256) {
            int rl = i >> 4;
            int c4 = (i & 15) * 4;
            int r = m0 + rl; if (r >= N) r = N - 1;
            float4 v = *(const float4*)(A + (size_t)r * DIM + h * KH + c4);
            float h0 = __bfloat162float(__float2bfloat16(v.x));
            float h1 = __bfloat162float(__float2bfloat16(v.y));
            float h2 = __bfloat162float(__float2bfloat16(v.z));
            float h3 = __bfloat162float(__float2bfloat16(v.w));
            int off = rl * BSTRIDE + c4 * 2;
            *(uint2*)(smem + off) =
                make_uint2(pack_bf16x2(h0, h1), pack_bf16x2(h2, h3));
            *(uint2*)(smem + HBUF + off) =
                make_uint2(pack_bf16x2(v.x - h0, v.y - h1),
                           pack_bf16x2(v.z - h2, v.w - h3));
        }
        // B half: Bt[n][k] rows 0..127, k in [h*64, h*64+64): 8 x 16B per row,
        // hi and lo buffers (i>>10 selects buffer).
        {
            const char* wh = (const char*)g_wconv[widx][0];
            const char* wl = (const char*)g_wconv[widx][1];
            for (int i = tid; i < 2048; i += 256) {
                int buf = i >> 10;
                int idx = i & 1023;
                int r = idx >> 3, c = (idx & 7) * 16;
                const char* src = (buf ? wl : wh) + (size_t)r * 256 + h * 128 + c;
                char* dst = smem + (buf ? 3 : 2) * HBUF + r * BSTRIDE + c;
                *(uint4*)dst = *(const uint4*)src;
            }
        }
        __syncthreads();

        #pragma unroll
        for (int s = 0; s < 4; s++) {
            const int k0 = s * 16;
            uint32_t ah[2][4], al[2][4];
            #pragma unroll
            for (int mt = 0; mt < 2; mt++) {
                int row = wm * 32 + mt * 16 + (lane & 15);
                int col = k0 + (lane >> 4) * 8;
                uint32_t off = row * BSTRIDE + col * 2;
                ldsm4(sAH + off, ah[mt][0], ah[mt][1], ah[mt][2], ah[mt][3]);
                ldsm4(sAL + off, al[mt][0], al[mt][1], al[mt][2], al[mt][3]);
            }
            #pragma unroll
            for (int np = 0; np < 4; np++) {
                uint32_t bh[2][2], bl[2][2];
                int g = lane >> 3;
                int row = wn * 64 + np * 16 + (g >> 1) * 8 + (lane & 7);
                int col = k0 + (g & 1) * 8;
                uint32_t off = row * BSTRIDE + col * 2;
                ldsm4(sBH + off, bh[0][0], bh[0][1], bh[1][0], bh[1][1]);
                ldsm4(sBL + off, bl[0][0], bl[0][1], bl[1][0], bl[1][1]);
                #pragma unroll
                for (int mt = 0; mt < 2; mt++)
                    #pragma unroll
                    for (int j = 0; j < 2; j++) {
                        int nt = 2 * np + j;
                        mma16816(acc[mt][nt], ah[mt][0], ah[mt][1], ah[mt][2], ah[mt][3],
                                 bh[j][0], bh[j][1]);
                        mma16816(acc[mt][nt], ah[mt][0], ah[mt][1], ah[mt][2], ah[mt][3],
                                 bl[j][0], bl[j][1]);
                        mma16816(acc[mt][nt], al[mt][0], al[mt][1], al[mt][2], al[mt][3],
                                 bh[j][0], bh[j][1]);
                    }
            }
        }
    }

    // --- Epilogue ---
    float2 bb[8];
    #pragma unroll
    for (int nt = 0; nt < 8; nt++) {
        int n = wn * 64 + nt * 8 + 2 * (lane & 3);
        bb[nt] = *(const float2*)(bias + n);
    }
    #pragma unroll
    for (int mt = 0; mt < 2; mt++) {
        #pragma unroll
        for (int half = 0; half < 2; half++) {
            int m = m0 + wm * 32 + mt * 16 + (lane >> 2) + half * 8;
            if (m >= N) continue;
            #pragma unroll
            for (int nt = 0; nt < 8; nt++) {
                int n = wn * 64 + nt * 8 + 2 * (lane & 3);
                float rx = acc[mt][nt][half * 2 + 0] + bb[nt].x;
                float ry = acc[mt][nt][half * 2 + 1] + bb[nt].y;
                if (mode == 1) {
                    float2 xv = *(const float2*)(extra + (size_t)m * DIM + n);
                    rx = xv.x * sigmoid_fast(rx);
                    ry = xv.y * sigmoid_fast(ry);
                } else if (mode == 2) {
                    float2 yv = *(const float2*)(extra + (size_t)m * DIM + n);
                    rx = tanh_fast(rx + yv.x);
                    ry = tanh_fast(ry + yv.y);
                }
                *(float2*)(out + (size_t)m * DIM + n) = make_float2(rx, ry);
            }
        }
    }
}

// ---------------------------------------------------------------------------
// Edge scatter: one warp per edge, red.global.add.v4.f32 per lane.
// ---------------------------------------------------------------------------
__global__ __launch_bounds__(256) void edge_scatter_kernel(int E)
{
    int warp = (int)((blockIdx.x * 256 + threadIdx.x) >> 5);
    if (warp >= E) return;
    int lane = threadIdx.x & 31;

    int2 rc = g_eidx[warp];
    const float* src = g_ga + (size_t)rc.y * DIM + lane * 4;
    float* dst       = g_aggr + (size_t)rc.x * DIM + lane * 4;

    float4 v = *(const float4*)src;
    asm volatile("red.global.add.v4.f32 [%0], {%1, %2, %3, %4};"
                 :: "l"(dst), "f"(v.x), "f"(v.y), "f"(v.z), "f"(v.w)
                 : "memory");
}

// ---------------------------------------------------------------------------
extern "C" void kernel_launch(void* const* d_in, const int* in_sizes, int n_in,
                              void* d_out, int out_size)
{
    const float* x    = (const float*)d_in[0];
    const void*  ei   = d_in[1];
    const float* Wn_w = (const float*)d_in[2];
    const float* Wn_b = (const float*)d_in[3];
    const float* Wg_w = (const float*)d_in[4];
    const float* Wg_b = (const float*)d_in[5];
    const float* Wa_w = (const float*)d_in[6];
    const float* Wa_b = (const float*)d_in[7];
    float* out = (float*)d_out;

    const int N = in_sizes[0] / DIM;
    const int E = in_sizes[1] / 2;

    float *p_yn, *p_ga, *p_aggr;
    cudaGetSymbolAddress((void**)&p_yn,   g_yn);
    cudaGetSymbolAddress((void**)&p_ga,   g_ga);
    cudaGetSymbolAddress((void**)&p_aggr, g_aggr);

    cudaFuncSetAttribute(gemm_mma_fused,
                         cudaFuncAttributeMaxDynamicSharedMemorySize, SM_TOTAL);

    prep_weights_kernel<<<24, 256>>>(Wn_w, Wg_w, Wa_w);
    detect_idx_kernel<<<1, 32>>>((const int*)ei);
    {
        int NF4 = N * DIM / 4;
        int total = NF4 > E ? NF4 : E;
        zero_pack_kernel<<<(total + 255) / 256, 256>>>(ei, E, NF4);
    }

    int gblocks = (N + 127) / 128;
    // y_n = x@Wn + bn
    gemm_mma_fused<<<gblocks, 256, SM_TOTAL>>>(x, 0, Wn_b, nullptr, p_yn, N, 0);
    // g = x * sigmoid(x@Wa + ba)
    gemm_mma_fused<<<gblocks, 256, SM_TOTAL>>>(x, 2, Wa_b, x, p_ga, N, 1);

    // aggr[row] += g[col]
    {
        long long threads = (long long)E * 32;
        int blocks = (int)((threads + 255) / 256);
        edge_scatter_kernel<<<blocks, 256>>>(E);
    }

    // out = tanh(aggr@Wg + bg + y_n)
    gemm_mma_fused<<<gblocks, 256, SM_TOTAL>>>(p_aggr, 1, Wg_b, p_yn, out, N, 2);
}

// round 10
// speedup vs baseline: 1.7403x; 1.0779x over previous
#include <cuda_runtime.h>
#include <cuda_bf16.h>
#include <math.h>
#include <stdint.h>

// ---------------------------------------------------------------------------
// AttentiveFPConv: out = tanh(x@Wn + bn + aggr@Wg + bg)
//   aggr[u] = sum_{e: row[e]==u} g[col[e]],  g[v] = x[v] * sigmoid((x@Wa+ba)[v])
// N = 40000, E = 640000, D = 128.
// Fusion: out = tanh([x | aggr] @ [Wn ; Wg] + (bn+bg))  -- one K=256 GEMM,
// y_n buffer eliminated.
// GEMMs: mma.sync m16n8k16 bf16, hi/lo split (3 terms), fp32 accum,
//        K-split SMEM (72KB) for 2 CTAs/SM, fast-math epilogue.
// Aggregation: warp-per-edge red.global.add.v4.f32.
// ---------------------------------------------------------------------------

#define NODES_MAX 40000
#define EDGES_MAX 640000
#define DIM 128

__device__ float g_ga[NODES_MAX * DIM];
__device__ float g_aggr[NODES_MAX * DIM];
__device__ int2  g_eidx[EDGES_MAX];
__device__ int   g_is64;
__device__ float g_bsum[DIM];
__device__ __align__(16) __nv_bfloat16 g_wconv[3][2][DIM * DIM];

// ---------------------------------------------------------------------------
__device__ __forceinline__ uint32_t smem_u32(const void* p) {
    uint32_t a;
    asm("{ .reg .u64 t; cvta.to.shared.u64 t, %1; cvt.u32.u64 %0, t; }" : "=r"(a) : "l"(p));
    return a;
}
__device__ __forceinline__ void ldsm4(uint32_t a, uint32_t& r0, uint32_t& r1,
                                      uint32_t& r2, uint32_t& r3) {
    asm volatile("ldmatrix.sync.aligned.m8n8.x4.shared.b16 {%0,%1,%2,%3}, [%4];"
                 : "=r"(r0), "=r"(r1), "=r"(r2), "=r"(r3) : "r"(a));
}
__device__ __forceinline__ void mma16816(float* c, uint32_t a0, uint32_t a1,
                                         uint32_t a2, uint32_t a3,
                                         uint32_t b0, uint32_t b1) {
    asm volatile(
        "mma.sync.aligned.m16n8k16.row.col.f32.bf16.bf16.f32 "
        "{%0,%1,%2,%3}, {%4,%5,%6,%7}, {%8,%9}, {%0,%1,%2,%3};"
        : "+f"(c[0]), "+f"(c[1]), "+f"(c[2]), "+f"(c[3])
        : "r"(a0), "r"(a1), "r"(a2), "r"(a3), "r"(b0), "r"(b1));
}
__device__ __forceinline__ uint32_t pack_bf16x2(float x, float y) {
    __nv_bfloat16 hx = __float2bfloat16(x), hy = __float2bfloat16(y);
    return (uint32_t)*(unsigned short*)&hx | ((uint32_t)*(unsigned short*)&hy << 16);
}
__device__ __forceinline__ float sigmoid_fast(float x) {
    float e = __expf(-x);
    return __fdividef(1.f, 1.f + e);
}
__device__ __forceinline__ float tanh_fast(float x) {
    float e = __expf(-2.f * x);
    return (1.f - e) * __fdividef(1.f, 1.f + e);
}

// ---------------------------------------------------------------------------
__global__ void detect_idx_kernel(const int* __restrict__ ei32) {
    if (threadIdx.x == 0 && blockIdx.x == 0) {
        int is64 = 1;
        #pragma unroll
        for (int i = 0; i < 32; i++)
            if (ei32[2 * i + 1] != 0) { is64 = 0; break; }
        g_is64 = is64;
    }
}

// Fused: zero aggr + pack edge indices + bias sum (bn+bg).
__global__ __launch_bounds__(256) void zero_pack_kernel(
    const void* __restrict__ ei, int E, int NF4,
    const float* __restrict__ bn, const float* __restrict__ bg)
{
    int i = blockIdx.x * blockDim.x + threadIdx.x;
    if (i < NF4)
        ((float4*)g_aggr)[i] = make_float4(0.f, 0.f, 0.f, 0.f);
    if (i < DIM)
        g_bsum[i] = bn[i] + bg[i];
    if (i < E) {
        int row, col;
        if (g_is64) {
            const long long* p = (const long long*)ei;
            row = (int)p[i]; col = (int)p[E + i];
        } else {
            const int* p = (const int*)ei;
            row = p[i]; col = p[E + i];
        }
        g_eidx[i] = make_int2(row, col);
    }
}

// prep weights: W[k][n] -> Bt[n][k] hi/lo bf16, coalesced via smem transpose.
__global__ __launch_bounds__(256) void prep_weights_kernel(
    const float* __restrict__ Wn, const float* __restrict__ Wg,
    const float* __restrict__ Wa)
{
    int mat = blockIdx.x >> 3;
    int kc  = (blockIdx.x & 7) * 16;
    const float* W = mat == 0 ? Wn : (mat == 1 ? Wg : Wa);
    __shared__ float tile[16][DIM];
    for (int i = threadIdx.x; i < 16 * DIM; i += 256) {
        int kk = i >> 7, n = i & 127;
        tile[kk][n] = W[(size_t)(kc + kk) * DIM + n];
    }
    __syncthreads();
    uint32_t* hi = (uint32_t*)g_wconv[mat][0];
    uint32_t* lo = (uint32_t*)g_wconv[mat][1];
    for (int i = threadIdx.x; i < DIM * 8; i += 256) {
        int n = i >> 3, kp = (i & 7) * 2;
        float v0 = tile[kp][n], v1 = tile[kp + 1][n];
        float h0 = __bfloat162float(__float2bfloat16(v0));
        float h1 = __bfloat162float(__float2bfloat16(v1));
        int idx = (n * DIM + kc + kp) >> 1;
        hi[idx] = pack_bf16x2(h0, h1);
        lo[idx] = pack_bf16x2(v0 - h0, v1 - h1);
    }
}

// ---------------------------------------------------------------------------
// mma.sync GEMM over nh half-K passes of 64. Half h reads A = (h<2?A0:A1)
// at k-offset (h&1)*64, weights g_wconv[(h<2?w0:w1)] at the same k-offset.
//   mode 1: out = extra * sigmoid(acc + bias)
//   mode 3: out = tanh(acc + bias)
// CTA 128x128 tile, 8 warps 4(M)x2(N), SMEM 72KB -> 2 CTAs/SM.
// ---------------------------------------------------------------------------
#define KH 64
#define BSTRIDE 144
#define HBUF (DIM * BSTRIDE)           // 18432
#define SM_TOTAL (4 * HBUF)            // 73728

__global__ __launch_bounds__(256, 2) void gemm_mma_fused(
    const float* __restrict__ A0, const float* __restrict__ A1,
    int w0, int w1, int nh,
    const float* __restrict__ bias, const float* __restrict__ extra,
    float* __restrict__ out, int N, int mode)
{
    extern __shared__ __align__(16) char smem[];
    const uint32_t sb  = smem_u32(smem);
    const uint32_t sAH = sb, sAL = sb + HBUF, sBH = sb + 2 * HBUF, sBL = sb + 3 * HBUF;
    const int tid = threadIdx.x, lane = tid & 31, wid = tid >> 5;
    const int m0 = blockIdx.x * 128;
    const int wm = wid & 3;
    const int wn = wid >> 2;

    float acc[2][8][4];
    #pragma unroll
    for (int mt = 0; mt < 2; mt++)
        #pragma unroll
        for (int nt = 0; nt < 8; nt++)
            #pragma unroll
            for (int q = 0; q < 4; q++) acc[mt][nt][q] = 0.f;

    #pragma unroll 1
    for (int h = 0; h < nh; h++) {
        if (h) __syncthreads();

        const float* A = (h < 2) ? A0 : A1;
        const int widx = (h < 2) ? w0 : w1;
        const int kh = (h & 1);

        // A half: 128 rows x 64 cols fp32, split hi/lo bf16
        for (int i = tid; i < 128 * 16; i += 256) {
            int rl = i >> 4;
            int c4 = (i & 15) * 4;
            int r = m0 + rl; if (r >= N) r = N - 1;
            float4 v = *(const float4*)(A + (size_t)r * DIM + kh * KH + c4);
            float h0 = __bfloat162float(__float2bfloat16(v.x));
            float h1 = __bfloat162float(__float2bfloat16(v.y));
            float h2 = __bfloat162float(__float2bfloat16(v.z));
            float h3 = __bfloat162float(__float2bfloat16(v.w));
            int off = rl * BSTRIDE + c4 * 2;
            *(uint2*)(smem + off) =
                make_uint2(pack_bf16x2(h0, h1), pack_bf16x2(h2, h3));
            *(uint2*)(smem + HBUF + off) =
                make_uint2(pack_bf16x2(v.x - h0, v.y - h1),
                           pack_bf16x2(v.z - h2, v.w - h3));
        }
        // B half: pre-split Bt[n][k], 8 x 16B per row, hi and lo buffers
        {
            const char* wh = (const char*)g_wconv[widx][0];
            const char* wl = (const char*)g_wconv[widx][1];
            for (int i = tid; i < 2048; i += 256) {
                int buf = i >> 10;
                int idx = i & 1023;
                int r = idx >> 3, c = (idx & 7) * 16;
                const char* src = (buf ? wl : wh) + (size_t)r * 256 + kh * 128 + c;
                char* dst = smem + (buf ? 3 : 2) * HBUF + r * BSTRIDE + c;
                *(uint4*)dst = *(const uint4*)src;
            }
        }
        __syncthreads();

        #pragma unroll
        for (int s = 0; s < 4; s++) {
            const int k0 = s * 16;
            uint32_t ah[2][4], al[2][4];
            #pragma unroll
            for (int mt = 0; mt < 2; mt++) {
                int row = wm * 32 + mt * 16 + (lane & 15);
                int col = k0 + (lane >> 4) * 8;
                uint32_t off = row * BSTRIDE + col * 2;
                ldsm4(sAH + off, ah[mt][0], ah[mt][1], ah[mt][2], ah[mt][3]);
                ldsm4(sAL + off, al[mt][0], al[mt][1], al[mt][2], al[mt][3]);
            }
            #pragma unroll
            for (int np = 0; np < 4; np++) {
                uint32_t bh[2][2], bl[2][2];
                int g = lane >> 3;
                int row = wn * 64 + np * 16 + (g >> 1) * 8 + (lane & 7);
                int col = k0 + (g & 1) * 8;
                uint32_t off = row * BSTRIDE + col * 2;
                ldsm4(sBH + off, bh[0][0], bh[0][1], bh[1][0], bh[1][1]);
                ldsm4(sBL + off, bl[0][0], bl[0][1], bl[1][0], bl[1][1]);
                #pragma unroll
                for (int mt = 0; mt < 2; mt++)
                    #pragma unroll
                    for (int j = 0; j < 2; j++) {
                        int nt = 2 * np + j;
                        mma16816(acc[mt][nt], ah[mt][0], ah[mt][1], ah[mt][2], ah[mt][3],
                                 bh[j][0], bh[j][1]);
                        mma16816(acc[mt][nt], ah[mt][0], ah[mt][1], ah[mt][2], ah[mt][3],
                                 bl[j][0], bl[j][1]);
                        mma16816(acc[mt][nt], al[mt][0], al[mt][1], al[mt][2], al[mt][3],
                                 bh[j][0], bh[j][1]);
                    }
            }
        }
    }

    // --- Epilogue ---
    float2 bb[8];
    #pragma unroll
    for (int nt = 0; nt < 8; nt++) {
        int n = wn * 64 + nt * 8 + 2 * (lane & 3);
        bb[nt] = *(const float2*)(bias + n);
    }
    #pragma unroll
    for (int mt = 0; mt < 2; mt++) {
        #pragma unroll
        for (int half = 0; half < 2; half++) {
            int m = m0 + wm * 32 + mt * 16 + (lane >> 2) + half * 8;
            if (m >= N) continue;
            #pragma unroll
            for (int nt = 0; nt < 8; nt++) {
                int n = wn * 64 + nt * 8 + 2 * (lane & 3);
                float rx = acc[mt][nt][half * 2 + 0] + bb[nt].x;
                float ry = acc[mt][nt][half * 2 + 1] + bb[nt].y;
                if (mode == 1) {
                    float2 xv = *(const float2*)(extra + (size_t)m * DIM + n);
                    rx = xv.x * sigmoid_fast(rx);
                    ry = xv.y * sigmoid_fast(ry);
                } else {   // mode 3
                    rx = tanh_fast(rx);
                    ry = tanh_fast(ry);
                }
                *(float2*)(out + (size_t)m * DIM + n) = make_float2(rx, ry);
            }
        }
    }
}

// ---------------------------------------------------------------------------
// Edge scatter: one warp per edge, red.global.add.v4.f32 per lane.
// ---------------------------------------------------------------------------
__global__ __launch_bounds__(256) void edge_scatter_kernel(int E)
{
    int warp = (int)((blockIdx.x * 256 + threadIdx.x) >> 5);
    if (warp >= E) return;
    int lane = threadIdx.x & 31;

    int2 rc = g_eidx[warp];
    const float* src = g_ga + (size_t)rc.y * DIM + lane * 4;
    float* dst       = g_aggr + (size_t)rc.x * DIM + lane * 4;

    float4 v = *(const float4*)src;
    asm volatile("red.global.add.v4.f32 [%0], {%1, %2, %3, %4};"
                 :: "l"(dst), "f"(v.x), "f"(v.y), "f"(v.z), "f"(v.w)
                 : "memory");
}

// ---------------------------------------------------------------------------
extern "C" void kernel_launch(void* const* d_in, const int* in_sizes, int n_in,
                              void* d_out, int out_size)
{
    const float* x    = (const float*)d_in[0];
    const void*  ei   = d_in[1];
    const float* Wn_w = (const float*)d_in[2];
    const float* Wn_b = (const float*)d_in[3];
    const float* Wg_w = (const float*)d_in[4];
    const float* Wg_b = (const float*)d_in[5];
    const float* Wa_w = (const float*)d_in[6];
    const float* Wa_b = (const float*)d_in[7];
    float* out = (float*)d_out;

    const int N = in_sizes[0] / DIM;
    const int E = in_sizes[1] / 2;

    float *p_ga, *p_aggr, *p_bsum;
    cudaGetSymbolAddress((void**)&p_ga,   g_ga);
    cudaGetSymbolAddress((void**)&p_aggr, g_aggr);
    cudaGetSymbolAddress((void**)&p_bsum, g_bsum);

    cudaFuncSetAttribute(gemm_mma_fused,
                         cudaFuncAttributeMaxDynamicSharedMemorySize, SM_TOTAL);

    prep_weights_kernel<<<24, 256>>>(Wn_w, Wg_w, Wa_w);
    detect_idx_kernel<<<1, 32>>>((const int*)ei);
    {
        int NF4 = N * DIM / 4;
        int total = NF4 > E ? NF4 : E;
        zero_pack_kernel<<<(total + 255) / 256, 256>>>(ei, E, NF4, Wn_b, Wg_b);
    }

    int gblocks = (N + 127) / 128;
    // g = x * sigmoid(x@Wa + ba)
    gemm_mma_fused<<<gblocks, 256, SM_TOTAL>>>(x, nullptr, 2, 2, 2,
                                               Wa_b, x, p_ga, N, 1);
    // aggr[row] += g[col]
    {
        long long threads = (long long)E * 32;
        int blocks = (int)((threads + 255) / 256);
        edge_scatter_kernel<<<blocks, 256>>>(E);
    }
    // out = tanh([x | aggr] @ [Wn ; Wg] + bn + bg)   (K=256, 4 halves)
    gemm_mma_fused<<<gblocks, 256, SM_TOTAL>>>(x, p_aggr, 0, 1, 4,
                                               p_bsum, nullptr, out, N, 3);
}